// round 1
// baseline (speedup 1.0000x reference)
#include <cuda_runtime.h>
#include <cub/cub.cuh>

#define NPIX   9216     // 96*96
#define NANCH  82944    // NPIX*9
#define PRE_N  6000
#define POS_N  300
#define NWORDS 94       // ceil(6000/64)

// ---------------- scratch (static device memory; no allocation) ----------------
__device__ float g_wt[1024*9*512];          // transposed rpn weights [c][ky*3+kx][oc]
__device__ float g_h[512*NPIX];             // relu(conv3x3) output [oc][pix]
__device__ float g_cls[18*NPIX];            // cls logits [ch][pix]
__device__ float g_reg[36*NPIX];            // reg deltas [ch][pix]
__device__ float g_prop[NANCH*4];           // unclipped proposals
__device__ float g_bbox[NANCH*4];           // clipped boxes
__device__ unsigned long long g_keys[NANCH];
__device__ unsigned long long g_keys_sorted[NANCH];
__device__ float g_topbox[PRE_N*4];
__device__ float g_topprob[PRE_N];
__device__ unsigned long long g_mask[PRE_N*NWORDS];
__device__ unsigned char g_cub_temp[8<<20];

// ---------------- weight transpose: w[oc][c][ky][kx] -> wt[c][kk][oc] ----------------
__global__ void transpose_w_kernel(const float* __restrict__ w) {
    int idx = blockIdx.x * 256 + threadIdx.x;          // over 512*1024*9, oc fastest
    if (idx >= 512*1024*9) return;
    int oc = idx % 512;
    int r  = idx / 512;
    int kk = r % 9;
    int c  = r / 9;
    g_wt[idx] = w[(oc*1024 + c)*9 + kk];
}

// ---------------- conv 3x3 (1024->512) + bias + relu ----------------
// grid: (8 oc-blocks of 64, 96 rows). block: 256 threads.
// thread (tid&31)*3 -> 3 pixels, (tid>>5)*8 -> 8 output channels. acc[8][3].
__global__ void __launch_bounds__(256) conv3x3_kernel(const float* __restrict__ x,
                                                      const float* __restrict__ b_rpn) {
    __shared__ float xs[3][8][104];                    // [ky][ci][xcol(+1 pad)]
    __shared__ __align__(16) float ws[8][3][3][64];    // [ci][ky][kx][oc]

    const int y    = blockIdx.y;
    const int ocb  = blockIdx.x * 64;
    const int tid  = threadIdx.x;
    const int px3  = (tid & 31) * 3;
    const int ocg  = tid >> 5;

    float acc[8][3];
#pragma unroll
    for (int o = 0; o < 8; o++)
#pragma unroll
        for (int p = 0; p < 3; p++) acc[o][p] = 0.f;

    for (int c0 = 0; c0 < 1024; c0 += 8) {
        // load x slab (3 rows x 8 cin x 96 cols, zero-padded)
        for (int idx = tid; idx < 3*8*104; idx += 256) {
            int ky = idx / (8*104);
            int r  = idx % (8*104);
            int ci = r / 104;
            int xc = r % 104;
            int gx = xc - 1, gy = y + ky - 1;
            float v = 0.f;
            if ((unsigned)gx < 96u && (unsigned)gy < 96u)
                v = x[(c0+ci)*NPIX + gy*96 + gx];
            xs[ky][ci][xc] = v;
        }
        // load weights (coalesced from transposed layout)
        for (int idx = tid; idx < 8*9*64; idx += 256) {
            int oc = idx & 63;
            int kk = (idx >> 6) % 9;
            int ci = idx / (64*9);
            ws[ci][kk/3][kk%3][oc] = g_wt[((c0+ci)*9 + kk)*512 + ocb + oc];
        }
        __syncthreads();

#pragma unroll 2
        for (int ci = 0; ci < 8; ci++) {
#pragma unroll
            for (int ky = 0; ky < 3; ky++) {
                float xv[5];
#pragma unroll
                for (int j = 0; j < 5; j++) xv[j] = xs[ky][ci][px3 + j];
#pragma unroll
                for (int kx = 0; kx < 3; kx++) {
                    const float4 w0 = *(const float4*)&ws[ci][ky][kx][ocg*8];
                    const float4 w1 = *(const float4*)&ws[ci][ky][kx][ocg*8 + 4];
#pragma unroll
                    for (int p = 0; p < 3; p++) {
                        float xvv = xv[kx + p];
                        acc[0][p] += w0.x * xvv;
                        acc[1][p] += w0.y * xvv;
                        acc[2][p] += w0.z * xvv;
                        acc[3][p] += w0.w * xvv;
                        acc[4][p] += w1.x * xvv;
                        acc[5][p] += w1.y * xvv;
                        acc[6][p] += w1.z * xvv;
                        acc[7][p] += w1.w * xvv;
                    }
                }
            }
        }
        __syncthreads();
    }

#pragma unroll
    for (int o = 0; o < 8; o++) {
        int oc = ocb + ocg*8 + o;
        float bias = b_rpn[oc];
#pragma unroll
        for (int p = 0; p < 3; p++) {
            float v = acc[o][p] + bias;
            g_h[oc*NPIX + y*96 + px3 + p] = v > 0.f ? v : 0.f;
        }
    }
}

// ---------------- 1x1 convs (512 -> 18 cls + 36 reg) ----------------
__global__ void __launch_bounds__(256) conv1x1_kernel(const float* __restrict__ wcls,
                                                      const float* __restrict__ bcls,
                                                      const float* __restrict__ wreg,
                                                      const float* __restrict__ breg) {
    int p = blockIdx.x * 256 + threadIdx.x;   // 9216 pixels exactly
    float acc[54];
#pragma unroll
    for (int o = 0; o < 54; o++) acc[o] = 0.f;

    for (int c = 0; c < 512; c += 4) {
        float v0 = g_h[(c+0)*NPIX + p];
        float v1 = g_h[(c+1)*NPIX + p];
        float v2 = g_h[(c+2)*NPIX + p];
        float v3 = g_h[(c+3)*NPIX + p];
#pragma unroll
        for (int o = 0; o < 18; o++) {
            float4 w = *(const float4*)(wcls + o*512 + c);
            acc[o] += w.x*v0; acc[o] += w.y*v1; acc[o] += w.z*v2; acc[o] += w.w*v3;
        }
#pragma unroll
        for (int o = 0; o < 36; o++) {
            float4 w = *(const float4*)(wreg + o*512 + c);
            acc[18+o] += w.x*v0; acc[18+o] += w.y*v1; acc[18+o] += w.z*v2; acc[18+o] += w.w*v3;
        }
    }
#pragma unroll
    for (int o = 0; o < 18; o++) g_cls[o*NPIX + p] = acc[o] + bcls[o];
#pragma unroll
    for (int o = 0; o < 36; o++) g_reg[o*NPIX + p] = acc[18+o] + breg[o];
}

// ---------------- decode anchors, softmax prob, sort keys ----------------
__global__ void decode_kernel(const float* __restrict__ anchors) {
    int a = blockIdx.x * 256 + threadIdx.x;   // 82944 exactly (324 blocks)
    int pix = a / 9, k = a % 9;

    float c0 = g_cls[(k*2 + 0)*NPIX + pix];
    float c1 = g_cls[(k*2 + 1)*NPIX + pix];
    float r0 = g_reg[(k*4 + 0)*NPIX + pix];
    float r1 = g_reg[(k*4 + 1)*NPIX + pix];
    float r2 = g_reg[(k*4 + 2)*NPIX + pix];
    float r3 = g_reg[(k*4 + 3)*NPIX + pix];

    float4 an = ((const float4*)anchors)[a];
    float aw = an.z - an.x + 1.f;
    float ah = an.w - an.y + 1.f;
    float ax = an.x + 0.5f*(aw - 1.f);
    float ay = an.y + 0.5f*(ah - 1.f);
    float px = ax + aw * r0;
    float py = ay + ah * r1;
    float pw = aw * expf(r2);
    float ph = ah * expf(r3);
    float x0 = px - 0.5f*(pw - 1.f);
    float y0 = py - 0.5f*(ph - 1.f);
    float x1 = px + 0.5f*(pw - 1.f);
    float y1 = py + 0.5f*(ph - 1.f);

    ((float4*)g_prop)[a] = make_float4(x0, y0, x1, y1);
    float4 cb;
    cb.x = fminf(fmaxf(x0, 0.f), 1535.f);
    cb.y = fminf(fmaxf(y0, 0.f), 1535.f);
    cb.z = fminf(fmaxf(x1, 0.f), 1535.f);
    cb.w = fminf(fmaxf(y1, 0.f), 1535.f);
    ((float4*)g_bbox)[a] = cb;

    // softmax exactly as jax.nn.softmax: subtract max, exp, normalize
    float m  = fmaxf(c0, c1);
    float e0 = expf(c0 - m);
    float e1 = expf(c1 - m);
    float prob = e1 / (e0 + e1);

    unsigned u = __float_as_uint(prob);       // prob > 0 always
    g_keys[a] = ((unsigned long long)(~u) << 32) | (unsigned)a;  // asc key = desc prob, asc idx
}

// ---------------- gather top-6000 ----------------
__global__ void gather_top_kernel() {
    int t = blockIdx.x * 256 + threadIdx.x;
    if (t >= PRE_N) return;
    unsigned long long key = g_keys_sorted[t];
    int a = (int)(key & 0xffffffffu);
    ((float4*)g_topbox)[t] = ((const float4*)g_bbox)[a];
    g_topprob[t] = __uint_as_float(~(unsigned)(key >> 32));
}

// ---------------- NMS suppression bitmask ----------------
__global__ void nms_mask_kernel() {
    const int rb = blockIdx.y, cb = blockIdx.x;
    if (cb < rb) return;
    __shared__ float4 cboxes[64];
    int cstart = cb * 64;
    int csize  = min(64, PRE_N - cstart);
    int t = threadIdx.x;
    if (t < csize) cboxes[t] = ((const float4*)g_topbox)[cstart + t];
    __syncthreads();

    int i = rb * 64 + t;
    if (i >= PRE_N) return;
    float4 b = ((const float4*)g_topbox)[i];
    float areai = (b.z - b.x + 1.f) * (b.w - b.y + 1.f);

    unsigned long long m = 0ull;
    int js = (rb == cb) ? t + 1 : 0;
    for (int j = js; j < csize; j++) {
        float4 c = cboxes[j];
        float iw = fminf(b.z, c.z) - fmaxf(b.x, c.x) + 1.f;
        float ih = fminf(b.w, c.w) - fmaxf(b.y, c.y) + 1.f;
        iw = fmaxf(iw, 0.f);
        ih = fmaxf(ih, 0.f);
        float inter = iw * ih;
        float areaj = (c.z - c.x + 1.f) * (c.w - c.y + 1.f);
        float iou = inter / (areai + areaj - inter);
        if (iou > 0.7f) m |= (1ull << j);
    }
    g_mask[(long long)i * NWORDS + cb] = m;
}

// ---------------- greedy NMS scan (1 block) + write filtered/probs ----------------
__global__ void __launch_bounds__(128) nms_scan_kernel(float* __restrict__ outF,
                                                       float* __restrict__ outP) {
    __shared__ int kept[PRE_N];
    __shared__ unsigned long long mw[64];
    __shared__ unsigned long long remv;
    __shared__ int kc;
    const int tid = threadIdx.x;
    if (tid == 0) kc = 0;
    __syncthreads();

    for (int g = 0; g < NWORDS; g++) {
        if (tid == 0) remv = 0ull;
        __syncthreads();
        // parallel OR of column g over all previously-kept rows
        unsigned long long part = 0ull;
        for (int t = tid; t < kc; t += 128)
            part |= g_mask[(long long)kept[t] * NWORDS + g];
        if (part) atomicOr(&remv, part);
        // preload diagonal-word rows for the serial bit scan
        if (tid < 64) {
            int i = g*64 + tid;
            mw[tid] = (i < PRE_N) ? g_mask[(long long)i * NWORDS + g] : 0ull;
        }
        __syncthreads();
        if (tid == 0) {
            unsigned long long r = remv;
            int lim = min(64, PRE_N - g*64);
            for (int b = 0; b < lim; b++) {
                if (!((r >> b) & 1ull)) {
                    kept[kc++] = g*64 + b;
                    r |= mw[b];
                }
            }
        }
        __syncthreads();
    }

    for (int rI = tid; rI < POS_N; rI += 128) {
        if (rI < kc) {
            int a = kept[rI];
            outF[rI*4 + 0] = g_topbox[a*4 + 0];
            outF[rI*4 + 1] = g_topbox[a*4 + 1];
            outF[rI*4 + 2] = g_topbox[a*4 + 2];
            outF[rI*4 + 3] = g_topbox[a*4 + 3];
            outP[rI] = g_topprob[a];
        } else {
            outF[rI*4 + 0] = 0.f; outF[rI*4 + 1] = 0.f;
            outF[rI*4 + 2] = 0.f; outF[rI*4 + 3] = 0.f;
            outP[rI] = 0.f;
        }
    }
}

// ---------------- gather proposals[valid_idx], cls[valid_idx] ----------------
__global__ void gather_valid_kernel(const int* __restrict__ vidx, int nv,
                                    float* __restrict__ out) {
    int i = blockIdx.x * 256 + threadIdx.x;
    if (i >= nv) return;
    int a = vidx[i];
    out[i*4 + 0] = g_prop[a*4 + 0];
    out[i*4 + 1] = g_prop[a*4 + 1];
    out[i*4 + 2] = g_prop[a*4 + 2];
    out[i*4 + 3] = g_prop[a*4 + 3];
    int pix = a / 9, k = a % 9;
    out[(long long)nv*4 + i*2 + 0] = g_cls[(k*2 + 0)*NPIX + pix];
    out[(long long)nv*4 + i*2 + 1] = g_cls[(k*2 + 1)*NPIX + pix];
}

// ---------------- host ----------------
extern "C" void kernel_launch(void* const* d_in, const int* in_sizes, int n_in,
                              void* d_out, int out_size) {
    // Robust input identification by element count (all sizes distinct).
    int ix=-1, iwr=-1, ibr=-1, iwc=-1, ibc=-1, iwg=-1, ibg=-1, ian=-1, ivi=-1;
    int nv = (out_size - (POS_N*4 + POS_N)) / 6;
    for (int i = 0; i < n_in; i++) {
        int s = in_sizes[i];
        if      (s == 1024*NPIX)     ix  = i;
        else if (s == 512*1024*9)    iwr = i;
        else if (s == 512)           ibr = i;
        else if (s == 18*512)        iwc = i;
        else if (s == 18)            ibc = i;
        else if (s == 36*512)        iwg = i;
        else if (s == 36)            ibg = i;
        else if (s == NANCH*4)       ian = i;
        else if (s == nv)            ivi = i;
    }
    if (ivi < 0) ivi = 8;   // fallback: dict order

    const float* x      = (const float*)d_in[ix];
    const float* w_rpn  = (const float*)d_in[iwr];
    const float* b_rpn  = (const float*)d_in[ibr];
    const float* w_cls  = (const float*)d_in[iwc];
    const float* b_cls  = (const float*)d_in[ibc];
    const float* w_reg  = (const float*)d_in[iwg];
    const float* b_reg  = (const float*)d_in[ibg];
    const float* anch   = (const float*)d_in[ian];
    const int*   vidx   = (const int*)d_in[ivi];
    float* out = (float*)d_out;

    transpose_w_kernel<<<(512*1024*9 + 255)/256, 256>>>(w_rpn);
    conv3x3_kernel<<<dim3(8, 96), 256>>>(x, b_rpn);
    conv1x1_kernel<<<NPIX/256, 256>>>(w_cls, b_cls, w_reg, b_reg);
    decode_kernel<<<NANCH/256, 256>>>(anch);

    void *d_temp, *d_kin, *d_kout;
    cudaGetSymbolAddress(&d_temp, g_cub_temp);
    cudaGetSymbolAddress(&d_kin,  g_keys);
    cudaGetSymbolAddress(&d_kout, g_keys_sorted);
    size_t temp_bytes = sizeof(g_cub_temp);
    cub::DeviceRadixSort::SortKeys(d_temp, temp_bytes,
                                   (const unsigned long long*)d_kin,
                                   (unsigned long long*)d_kout,
                                   NANCH, 0, 64, (cudaStream_t)0);

    gather_top_kernel<<<(PRE_N + 255)/256, 256>>>();
    nms_mask_kernel<<<dim3(NWORDS, NWORDS), 64>>>();
    nms_scan_kernel<<<1, 128>>>(out + (long long)nv*6,
                                out + (long long)nv*6 + POS_N*4);
    gather_valid_kernel<<<(nv + 255)/256, 256>>>(vidx, nv, out);
}

// round 2
// speedup vs baseline: 1.0141x; 1.0141x over previous
#include <cuda_runtime.h>
#include <cub/cub.cuh>

#define NPIX   9216     // 96*96
#define NANCH  82944    // NPIX*9
#define PRE_N  6000
#define POS_N  300
#define NWORDS 94       // ceil(6000/64)

// ---------------- scratch (static device memory; no allocation) ----------------
__device__ float g_wt[1024*9*512];          // transposed rpn weights [c*9+kk][oc]
__device__ float g_h[512*NPIX];             // relu(conv3x3) output [oc][pix]
__device__ float g_cls[18*NPIX];            // cls logits [ch][pix]
__device__ float g_reg[36*NPIX];            // reg deltas [ch][pix]
__device__ float g_prop[NANCH*4];           // unclipped proposals
__device__ float g_bbox[NANCH*4];           // clipped boxes
__device__ unsigned long long g_keys[NANCH];
__device__ unsigned long long g_keys_sorted[NANCH];
__device__ float g_topbox[PRE_N*4];
__device__ float g_topprob[PRE_N];
__device__ unsigned long long g_mask[PRE_N*NWORDS];
__device__ unsigned char g_cub_temp[8<<20];

// ---------------- packed f32x2 helpers (sm_103a FFMA2) ----------------
__device__ __forceinline__ void ffma2(unsigned long long &d,
                                      unsigned long long a,
                                      unsigned long long b) {
    asm("fma.rn.f32x2 %0, %1, %2, %0;" : "+l"(d) : "l"(a), "l"(b));
}
__device__ __forceinline__ float f2_lo(unsigned long long v) {
    return __uint_as_float((unsigned)(v & 0xffffffffull));
}
__device__ __forceinline__ float f2_hi(unsigned long long v) {
    return __uint_as_float((unsigned)(v >> 32));
}

// ---------------- tiled weight transpose: w[oc][c*9+kk] -> g_wt[c*9+kk][oc] ----------------
// view w as [512][9216] row-major; output [9216][512].
__global__ void __launch_bounds__(256) transpose_w_kernel(const float* __restrict__ w) {
    __shared__ float tile[32][33];
    int cko = blockIdx.x * 32;    // ck tile origin (9216/32 = 288)
    int oco = blockIdx.y * 32;    // oc tile origin (512/32 = 16)
    int tx = threadIdx.x & 31;
    int ty = threadIdx.x >> 5;    // 0..7
    // read: rows = oc, cols = ck (coalesced along ck)
#pragma unroll
    for (int r = 0; r < 32; r += 8)
        tile[ty + r][tx] = w[(long long)(oco + ty + r) * 9216 + cko + tx];
    __syncthreads();
    // write: rows = ck, cols = oc (coalesced along oc)
#pragma unroll
    for (int r = 0; r < 32; r += 8)
        g_wt[(long long)(cko + ty + r) * 512 + oco + tx] = tile[tx][ty + r];
}

// ---------------- conv 3x3 (1024->512) + bias + relu, FFMA2 ----------------
// grid: (8 oc-blocks of 64, 96 rows). block: 256 threads.
// thread (tid&31)*3 -> 3 pixels, (tid>>5)*8 -> 8 output channels (4 f32x2 pairs).
__global__ void __launch_bounds__(256) conv3x3_kernel(const float* __restrict__ x,
                                                      const float* __restrict__ b_rpn) {
    __shared__ unsigned long long xs2[3][8][104];      // [ky][ci][xcol], value dup'd in both lanes
    __shared__ __align__(16) float ws[8][3][3][64];    // [ci][ky][kx][oc]

    const int y    = blockIdx.y;
    const int ocb  = blockIdx.x * 64;
    const int tid  = threadIdx.x;
    const int px3  = (tid & 31) * 3;
    const int ocg  = tid >> 5;

    unsigned long long acc[4][3];
#pragma unroll
    for (int o = 0; o < 4; o++)
#pragma unroll
        for (int p = 0; p < 3; p++) acc[o][p] = 0ull;

    for (int c0 = 0; c0 < 1024; c0 += 8) {
        // load x slab (3 rows x 8 cin x 96 cols, zero-padded, duplicated into f32x2)
        for (int idx = tid; idx < 3*8*104; idx += 256) {
            int ky = idx / (8*104);
            int r  = idx % (8*104);
            int ci = r / 104;
            int xc = r % 104;
            int gx = xc - 1, gy = y + ky - 1;
            float v = 0.f;
            if ((unsigned)gx < 96u && (unsigned)gy < 96u)
                v = x[(c0+ci)*NPIX + gy*96 + gx];
            unsigned u = __float_as_uint(v);
            xs2[ky][ci][xc] = ((unsigned long long)u << 32) | u;
        }
        // load weights (coalesced from transposed layout)
        for (int idx = tid; idx < 8*9*64; idx += 256) {
            int oc = idx & 63;
            int kk = (idx >> 6) % 9;
            int ci = idx / (64*9);
            ws[ci][kk/3][kk%3][oc] = g_wt[((c0+ci)*9 + kk)*512 + ocb + oc];
        }
        __syncthreads();

#pragma unroll 2
        for (int ci = 0; ci < 8; ci++) {
#pragma unroll
            for (int ky = 0; ky < 3; ky++) {
                unsigned long long xp[5];
#pragma unroll
                for (int j = 0; j < 5; j++) xp[j] = xs2[ky][ci][px3 + j];
#pragma unroll
                for (int kx = 0; kx < 3; kx++) {
                    const unsigned long long* wp =
                        (const unsigned long long*)&ws[ci][ky][kx][ocg*8];
                    unsigned long long w0 = wp[0], w1 = wp[1], w2 = wp[2], w3 = wp[3];
#pragma unroll
                    for (int p = 0; p < 3; p++) {
                        ffma2(acc[0][p], w0, xp[kx + p]);
                        ffma2(acc[1][p], w1, xp[kx + p]);
                        ffma2(acc[2][p], w2, xp[kx + p]);
                        ffma2(acc[3][p], w3, xp[kx + p]);
                    }
                }
            }
        }
        __syncthreads();
    }

#pragma unroll
    for (int o = 0; o < 4; o++) {
        int oc0 = ocb + ocg*8 + 2*o;
        float b0 = b_rpn[oc0], b1 = b_rpn[oc0 + 1];
#pragma unroll
        for (int p = 0; p < 3; p++) {
            float v0 = f2_lo(acc[o][p]) + b0;
            float v1 = f2_hi(acc[o][p]) + b1;
            g_h[(oc0    )*NPIX + y*96 + px3 + p] = v0 > 0.f ? v0 : 0.f;
            g_h[(oc0 + 1)*NPIX + y*96 + px3 + p] = v1 > 0.f ? v1 : 0.f;
        }
    }
}

// ---------------- 1x1 convs (512 -> 18 cls + 36 reg) ----------------
__global__ void __launch_bounds__(256) conv1x1_kernel(const float* __restrict__ wcls,
                                                      const float* __restrict__ bcls,
                                                      const float* __restrict__ wreg,
                                                      const float* __restrict__ breg) {
    int p = blockIdx.x * 256 + threadIdx.x;   // 9216 pixels exactly
    float acc[54];
#pragma unroll
    for (int o = 0; o < 54; o++) acc[o] = 0.f;

    for (int c = 0; c < 512; c += 4) {
        float v0 = g_h[(c+0)*NPIX + p];
        float v1 = g_h[(c+1)*NPIX + p];
        float v2 = g_h[(c+2)*NPIX + p];
        float v3 = g_h[(c+3)*NPIX + p];
#pragma unroll
        for (int o = 0; o < 18; o++) {
            float4 w = *(const float4*)(wcls + o*512 + c);
            acc[o] += w.x*v0; acc[o] += w.y*v1; acc[o] += w.z*v2; acc[o] += w.w*v3;
        }
#pragma unroll
        for (int o = 0; o < 36; o++) {
            float4 w = *(const float4*)(wreg + o*512 + c);
            acc[18+o] += w.x*v0; acc[18+o] += w.y*v1; acc[18+o] += w.z*v2; acc[18+o] += w.w*v3;
        }
    }
#pragma unroll
    for (int o = 0; o < 18; o++) g_cls[o*NPIX + p] = acc[o] + bcls[o];
#pragma unroll
    for (int o = 0; o < 36; o++) g_reg[o*NPIX + p] = acc[18+o] + breg[o];
}

// ---------------- decode anchors, softmax prob, sort keys ----------------
__global__ void decode_kernel(const float* __restrict__ anchors) {
    int a = blockIdx.x * 256 + threadIdx.x;   // 82944 exactly (324 blocks)
    int pix = a / 9, k = a % 9;

    float c0 = g_cls[(k*2 + 0)*NPIX + pix];
    float c1 = g_cls[(k*2 + 1)*NPIX + pix];
    float r0 = g_reg[(k*4 + 0)*NPIX + pix];
    float r1 = g_reg[(k*4 + 1)*NPIX + pix];
    float r2 = g_reg[(k*4 + 2)*NPIX + pix];
    float r3 = g_reg[(k*4 + 3)*NPIX + pix];

    float4 an = ((const float4*)anchors)[a];
    float aw = an.z - an.x + 1.f;
    float ah = an.w - an.y + 1.f;
    float ax = an.x + 0.5f*(aw - 1.f);
    float ay = an.y + 0.5f*(ah - 1.f);
    float px = ax + aw * r0;
    float py = ay + ah * r1;
    float pw = aw * expf(r2);
    float ph = ah * expf(r3);
    float x0 = px - 0.5f*(pw - 1.f);
    float y0 = py - 0.5f*(ph - 1.f);
    float x1 = px + 0.5f*(pw - 1.f);
    float y1 = py + 0.5f*(ph - 1.f);

    ((float4*)g_prop)[a] = make_float4(x0, y0, x1, y1);
    float4 cb;
    cb.x = fminf(fmaxf(x0, 0.f), 1535.f);
    cb.y = fminf(fmaxf(y0, 0.f), 1535.f);
    cb.z = fminf(fmaxf(x1, 0.f), 1535.f);
    cb.w = fminf(fmaxf(y1, 0.f), 1535.f);
    ((float4*)g_bbox)[a] = cb;

    // softmax exactly as jax.nn.softmax: subtract max, exp, normalize
    float m  = fmaxf(c0, c1);
    float e0 = expf(c0 - m);
    float e1 = expf(c1 - m);
    float prob = e1 / (e0 + e1);

    unsigned u = __float_as_uint(prob);       // prob > 0 always
    g_keys[a] = ((unsigned long long)(~u) << 32) | (unsigned)a;  // asc key = desc prob, asc idx
}

// ---------------- gather top-6000 ----------------
__global__ void gather_top_kernel() {
    int t = blockIdx.x * 256 + threadIdx.x;
    if (t >= PRE_N) return;
    unsigned long long key = g_keys_sorted[t];
    int a = (int)(key & 0xffffffffu);
    ((float4*)g_topbox)[t] = ((const float4*)g_bbox)[a];
    g_topprob[t] = __uint_as_float(~(unsigned)(key >> 32));
}

// ---------------- NMS suppression bitmask ----------------
__global__ void nms_mask_kernel() {
    const int rb = blockIdx.y, cb = blockIdx.x;
    if (cb < rb) return;
    __shared__ float4 cboxes[64];
    int cstart = cb * 64;
    int csize  = min(64, PRE_N - cstart);
    int t = threadIdx.x;
    if (t < csize) cboxes[t] = ((const float4*)g_topbox)[cstart + t];
    __syncthreads();

    int i = rb * 64 + t;
    if (i >= PRE_N) return;
    float4 b = ((const float4*)g_topbox)[i];
    float areai = (b.z - b.x + 1.f) * (b.w - b.y + 1.f);

    unsigned long long m = 0ull;
    int js = (rb == cb) ? t + 1 : 0;
    for (int j = js; j < csize; j++) {
        float4 c = cboxes[j];
        float iw = fminf(b.z, c.z) - fmaxf(b.x, c.x) + 1.f;
        float ih = fminf(b.w, c.w) - fmaxf(b.y, c.y) + 1.f;
        iw = fmaxf(iw, 0.f);
        ih = fmaxf(ih, 0.f);
        float inter = iw * ih;
        float areaj = (c.z - c.x + 1.f) * (c.w - c.y + 1.f);
        float iou = inter / (areai + areaj - inter);
        if (iou > 0.7f) m |= (1ull << j);
    }
    g_mask[(long long)i * NWORDS + cb] = m;
}

// ---------------- greedy NMS scan (1 block) + write filtered/probs ----------------
__global__ void __launch_bounds__(128) nms_scan_kernel(float* __restrict__ outF,
                                                       float* __restrict__ outP) {
    __shared__ int kept[PRE_N];
    __shared__ unsigned long long mw[64];
    __shared__ unsigned long long remv;
    __shared__ int kc;
    const int tid = threadIdx.x;
    if (tid == 0) kc = 0;
    __syncthreads();

    for (int g = 0; g < NWORDS; g++) {
        if (tid == 0) remv = 0ull;
        __syncthreads();
        // parallel OR of column g over all previously-kept rows
        unsigned long long part = 0ull;
        for (int t = tid; t < kc; t += 128)
            part |= g_mask[(long long)kept[t] * NWORDS + g];
        if (part) atomicOr(&remv, part);
        // preload diagonal-word rows for the serial bit scan
        if (tid < 64) {
            int i = g*64 + tid;
            mw[tid] = (i < PRE_N) ? g_mask[(long long)i * NWORDS + g] : 0ull;
        }
        __syncthreads();
        if (tid == 0) {
            unsigned long long r = remv;
            int lim = min(64, PRE_N - g*64);
            for (int b = 0; b < lim; b++) {
                if (!((r >> b) & 1ull)) {
                    kept[kc++] = g*64 + b;
                    r |= mw[b];
                }
            }
        }
        __syncthreads();
    }

    for (int rI = tid; rI < POS_N; rI += 128) {
        if (rI < kc) {
            int a = kept[rI];
            outF[rI*4 + 0] = g_topbox[a*4 + 0];
            outF[rI*4 + 1] = g_topbox[a*4 + 1];
            outF[rI*4 + 2] = g_topbox[a*4 + 2];
            outF[rI*4 + 3] = g_topbox[a*4 + 3];
            outP[rI] = g_topprob[a];
        } else {
            outF[rI*4 + 0] = 0.f; outF[rI*4 + 1] = 0.f;
            outF[rI*4 + 2] = 0.f; outF[rI*4 + 3] = 0.f;
            outP[rI] = 0.f;
        }
    }
}

// ---------------- gather proposals[valid_idx], cls[valid_idx] ----------------
__global__ void gather_valid_kernel(const int* __restrict__ vidx, int nv,
                                    float* __restrict__ out) {
    int i = blockIdx.x * 256 + threadIdx.x;
    if (i >= nv) return;
    int a = vidx[i];
    out[i*4 + 0] = g_prop[a*4 + 0];
    out[i*4 + 1] = g_prop[a*4 + 1];
    out[i*4 + 2] = g_prop[a*4 + 2];
    out[i*4 + 3] = g_prop[a*4 + 3];
    int pix = a / 9, k = a % 9;
    out[(long long)nv*4 + i*2 + 0] = g_cls[(k*2 + 0)*NPIX + pix];
    out[(long long)nv*4 + i*2 + 1] = g_cls[(k*2 + 1)*NPIX + pix];
}

// ---------------- host ----------------
extern "C" void kernel_launch(void* const* d_in, const int* in_sizes, int n_in,
                              void* d_out, int out_size) {
    // Robust input identification by element count (all sizes distinct).
    int ix=-1, iwr=-1, ibr=-1, iwc=-1, ibc=-1, iwg=-1, ibg=-1, ian=-1, ivi=-1;
    int nv = (out_size - (POS_N*4 + POS_N)) / 6;
    for (int i = 0; i < n_in; i++) {
        int s = in_sizes[i];
        if      (s == 1024*NPIX)     ix  = i;
        else if (s == 512*1024*9)    iwr = i;
        else if (s == 512)           ibr = i;
        else if (s == 18*512)        iwc = i;
        else if (s == 18)            ibc = i;
        else if (s == 36*512)        iwg = i;
        else if (s == 36)            ibg = i;
        else if (s == NANCH*4)       ian = i;
        else if (s == nv)            ivi = i;
    }
    if (ivi < 0) ivi = 8;   // fallback: dict order

    const float* x      = (const float*)d_in[ix];
    const float* w_rpn  = (const float*)d_in[iwr];
    const float* b_rpn  = (const float*)d_in[ibr];
    const float* w_cls  = (const float*)d_in[iwc];
    const float* b_cls  = (const float*)d_in[ibc];
    const float* w_reg  = (const float*)d_in[iwg];
    const float* b_reg  = (const float*)d_in[ibg];
    const float* anch   = (const float*)d_in[ian];
    const int*   vidx   = (const int*)d_in[ivi];
    float* out = (float*)d_out;

    transpose_w_kernel<<<dim3(288, 16), 256>>>(w_rpn);
    conv3x3_kernel<<<dim3(8, 96), 256>>>(x, b_rpn);
    conv1x1_kernel<<<NPIX/256, 256>>>(w_cls, b_cls, w_reg, b_reg);
    decode_kernel<<<NANCH/256, 256>>>(anch);

    void *d_temp, *d_kin, *d_kout;
    cudaGetSymbolAddress(&d_temp, g_cub_temp);
    cudaGetSymbolAddress(&d_kin,  g_keys);
    cudaGetSymbolAddress(&d_kout, g_keys_sorted);
    size_t temp_bytes = sizeof(g_cub_temp);
    cub::DeviceRadixSort::SortKeys(d_temp, temp_bytes,
                                   (const unsigned long long*)d_kin,
                                   (unsigned long long*)d_kout,
                                   NANCH, 0, 64, (cudaStream_t)0);

    gather_top_kernel<<<(PRE_N + 255)/256, 256>>>();
    nms_mask_kernel<<<dim3(NWORDS, NWORDS), 64>>>();
    nms_scan_kernel<<<1, 128>>>(out + (long long)nv*6,
                                out + (long long)nv*6 + POS_N*4);
    gather_valid_kernel<<<(nv + 255)/256, 256>>>(vidx, nv, out);
}

// round 5
// speedup vs baseline: 1.3211x; 1.3028x over previous
#include <cuda_runtime.h>
#include <cub/cub.cuh>

#define NPIX   9216     // 96*96
#define NANCH  82944    // NPIX*9
#define PRE_N  6000
#define POS_N  300
#define NWORDS 94       // ceil(6000/64)

// ---------------- scratch (static device memory; no allocation) ----------------
__device__ float g_wt[1024*9*512];          // transposed rpn weights [ci*9+kk][oc]
__device__ float g_h[512*NPIX];             // relu(conv3x3) output [oc][pix]
__device__ float g_cls[18*NPIX];            // cls logits [ch][pix]
__device__ float g_reg[36*NPIX];            // reg deltas [ch][pix]
__device__ float g_prop[NANCH*4];           // unclipped proposals
__device__ float g_bbox[NANCH*4];           // clipped boxes
__device__ unsigned long long g_keys[NANCH];
__device__ unsigned long long g_keys_sorted[NANCH];
__device__ float g_topbox[PRE_N*4];
__device__ float g_topprob[PRE_N];
__device__ unsigned long long g_mask[PRE_N*NWORDS];
__device__ unsigned char g_cub_temp[8<<20];

// ---------------- packed f32x2 helpers (sm_103a FFMA2) ----------------
__device__ __forceinline__ void ffma2(unsigned long long &d,
                                      unsigned long long a,
                                      unsigned long long b) {
    asm("fma.rn.f32x2 %0, %1, %2, %0;" : "+l"(d) : "l"(a), "l"(b));
}
__device__ __forceinline__ float f2_lo(unsigned long long v) {
    return __uint_as_float((unsigned)(v & 0xffffffffull));
}
__device__ __forceinline__ float f2_hi(unsigned long long v) {
    return __uint_as_float((unsigned)(v >> 32));
}

// ---------------- tiled weight transpose: w[oc][ci*9+kk] -> g_wt[ci*9+kk][oc] ----------------
__global__ void __launch_bounds__(256) transpose_w_kernel(const float* __restrict__ w) {
    __shared__ float tile[32][33];
    int cko = blockIdx.x * 32;    // ck tile origin (9216/32 = 288)
    int oco = blockIdx.y * 32;    // oc tile origin (512/32 = 16)
    int tx = threadIdx.x & 31;
    int ty = threadIdx.x >> 5;    // 0..7
#pragma unroll
    for (int r = 0; r < 32; r += 8)
        tile[ty + r][tx] = w[(long long)(oco + ty + r) * 9216 + cko + tx];
    __syncthreads();
#pragma unroll
    for (int r = 0; r < 32; r += 8)
        g_wt[(long long)(cko + ty + r) * 512 + oco + tx] = tile[tx][ty + r];
}

// ---------------- conv 3x3 (1024->512) + bias + relu, FFMA2 register GEMM ----------------
// Grid (72, 2): 72 pixel tiles (4 rows x 32 cols), 2 oc halves of 256.
// Block 256: og = tid>>3 (8 oc), pg = tid&7 -> (row r = pg&3, col half ch = pg>>2, 16 pix).
// Thread: 16 pix x 8 oc = 64 f32x2 accumulators.
__global__ void __launch_bounds__(256, 1)
conv3x3_kernel(const float* __restrict__ x, const float* __restrict__ b_rpn) {
    __shared__ float2 xs[2][6][36];     // x slab, value duplicated in both lanes
    __shared__ float  ws[2][9][256];    // weights [tap][oc]

    const int tid = threadIdx.x;
    const int og  = tid >> 3;           // 0..31
    const int pg  = tid & 7;            // 0..7
    const int r   = pg & 3;
    const int cbase = (pg >> 2) * 16;
    const int bx  = blockIdx.x;
    const int y0  = (bx / 3) * 4;
    const int x0  = (bx % 3) * 32;
    const int ocb = blockIdx.y * 256;

    // xs fill mapping (threads 0..203): 6 rows x 34 cols, zero-padded at image edge
    const int xrow = tid / 34;
    const int xcol = tid % 34;
    const int gy = y0 - 1 + xrow;
    const int gx = x0 - 1 + xcol;
    const bool xok = (tid < 204) && ((unsigned)gy < 96u) && ((unsigned)gx < 96u);
    const long long xoff = (long long)gy * 96 + gx;

    unsigned long long acc[16][4];
#pragma unroll
    for (int p = 0; p < 16; p++)
#pragma unroll
        for (int q = 0; q < 4; q++) acc[p][q] = 0ull;

    // prefetch ci = 0
    float xv = xok ? x[xoff] : 0.f;
    float wv[9];
#pragma unroll
    for (int j = 0; j < 9; j++) wv[j] = g_wt[(size_t)j * 512 + ocb + tid];

    // stage ci = 0 into buffer 0
    if (tid < 204) xs[0][xrow][xcol] = make_float2(xv, xv);
#pragma unroll
    for (int j = 0; j < 9; j++) ws[0][j][tid] = wv[j];

    for (int ci = 0; ci < 1024; ci++) {
        const int b = ci & 1;
        if (ci < 1023) {
            xv = xok ? x[(long long)(ci + 1) * NPIX + xoff] : 0.f;
#pragma unroll
            for (int j = 0; j < 9; j++)
                wv[j] = g_wt[((size_t)(ci + 1) * 9 + j) * 512 + ocb + tid];
        }
        __syncthreads();   // buffer b fully staged

#pragma unroll
        for (int dy = 0; dy < 3; dy++) {
            unsigned long long xr[18];
#pragma unroll
            for (int j = 0; j < 18; j++)
                xr[j] = *(const unsigned long long*)&xs[b][r + dy][cbase + j];
#pragma unroll
            for (int dx = 0; dx < 3; dx++) {
                const unsigned long long* wp =
                    (const unsigned long long*)&ws[b][dy * 3 + dx][og * 8];
                const unsigned long long w0 = wp[0], w1 = wp[1],
                                         w2 = wp[2], w3 = wp[3];
#pragma unroll
                for (int p = 0; p < 16; p++) {
                    ffma2(acc[p][0], w0, xr[p + dx]);
                    ffma2(acc[p][1], w1, xr[p + dx]);
                    ffma2(acc[p][2], w2, xr[p + dx]);
                    ffma2(acc[p][3], w3, xr[p + dx]);
                }
            }
        }

        if (ci < 1023) {
            __syncthreads();   // all compute on old buffer done
            const int nb = b ^ 1;
            if (tid < 204) xs[nb][xrow][xcol] = make_float2(xv, xv);
#pragma unroll
            for (int j = 0; j < 9; j++) ws[nb][j][tid] = wv[j];
        }
    }

    // epilogue: bias + relu -> g_h[oc][pix]
#pragma unroll
    for (int q = 0; q < 4; q++) {
        const int oc0 = ocb + og * 8 + 2 * q;
        const float b0 = b_rpn[oc0], b1 = b_rpn[oc0 + 1];
#pragma unroll
        for (int p = 0; p < 16; p++) {
            const int pix = (y0 + r) * 96 + x0 + cbase + p;
            float v0 = f2_lo(acc[p][q]) + b0;
            float v1 = f2_hi(acc[p][q]) + b1;
            g_h[(size_t)oc0 * NPIX + pix]       = v0 > 0.f ? v0 : 0.f;
            g_h[(size_t)(oc0 + 1) * NPIX + pix] = v1 > 0.f ? v1 : 0.f;
        }
    }
}

// ---------------- 1x1 convs (512 -> 18 cls + 36 reg) ----------------
__global__ void __launch_bounds__(256) conv1x1_kernel(const float* __restrict__ wcls,
                                                      const float* __restrict__ bcls,
                                                      const float* __restrict__ wreg,
                                                      const float* __restrict__ breg) {
    int p = blockIdx.x * 256 + threadIdx.x;   // 9216 pixels exactly
    float acc[54];
#pragma unroll
    for (int o = 0; o < 54; o++) acc[o] = 0.f;

    for (int c = 0; c < 512; c += 4) {
        float v0 = g_h[(c+0)*NPIX + p];
        float v1 = g_h[(c+1)*NPIX + p];
        float v2 = g_h[(c+2)*NPIX + p];
        float v3 = g_h[(c+3)*NPIX + p];
#pragma unroll
        for (int o = 0; o < 18; o++) {
            float4 w = *(const float4*)(wcls + o*512 + c);
            acc[o] += w.x*v0; acc[o] += w.y*v1; acc[o] += w.z*v2; acc[o] += w.w*v3;
        }
#pragma unroll
        for (int o = 0; o < 36; o++) {
            float4 w = *(const float4*)(wreg + o*512 + c);
            acc[18+o] += w.x*v0; acc[18+o] += w.y*v1; acc[18+o] += w.z*v2; acc[18+o] += w.w*v3;
        }
    }
#pragma unroll
    for (int o = 0; o < 18; o++) g_cls[o*NPIX + p] = acc[o] + bcls[o];
#pragma unroll
    for (int o = 0; o < 36; o++) g_reg[o*NPIX + p] = acc[18+o] + breg[o];
}

// ---------------- decode anchors, softmax prob, sort keys ----------------
__global__ void decode_kernel(const float* __restrict__ anchors) {
    int a = blockIdx.x * 256 + threadIdx.x;   // 82944 exactly (324 blocks)
    int pix = a / 9, k = a % 9;

    float c0 = g_cls[(k*2 + 0)*NPIX + pix];
    float c1 = g_cls[(k*2 + 1)*NPIX + pix];
    float r0 = g_reg[(k*4 + 0)*NPIX + pix];
    float r1 = g_reg[(k*4 + 1)*NPIX + pix];
    float r2 = g_reg[(k*4 + 2)*NPIX + pix];
    float r3 = g_reg[(k*4 + 3)*NPIX + pix];

    float4 an = ((const float4*)anchors)[a];
    float aw = an.z - an.x + 1.f;
    float ah = an.w - an.y + 1.f;
    float ax = an.x + 0.5f*(aw - 1.f);
    float ay = an.y + 0.5f*(ah - 1.f);
    float px = ax + aw * r0;
    float py = ay + ah * r1;
    float pw = aw * expf(r2);
    float ph = ah * expf(r3);
    float x0 = px - 0.5f*(pw - 1.f);
    float y0 = py - 0.5f*(ph - 1.f);
    float x1 = px + 0.5f*(pw - 1.f);
    float y1 = py + 0.5f*(ph - 1.f);

    ((float4*)g_prop)[a] = make_float4(x0, y0, x1, y1);
    float4 cb;
    cb.x = fminf(fmaxf(x0, 0.f), 1535.f);
    cb.y = fminf(fmaxf(y0, 0.f), 1535.f);
    cb.z = fminf(fmaxf(x1, 0.f), 1535.f);
    cb.w = fminf(fmaxf(y1, 0.f), 1535.f);
    ((float4*)g_bbox)[a] = cb;

    float m  = fmaxf(c0, c1);
    float e0 = expf(c0 - m);
    float e1 = expf(c1 - m);
    float prob = e1 / (e0 + e1);

    unsigned u = __float_as_uint(prob);       // prob > 0 always
    g_keys[a] = ((unsigned long long)(~u) << 32) | (unsigned)a;  // asc key = desc prob, asc idx
}

// ---------------- gather top-6000 ----------------
__global__ void gather_top_kernel() {
    int t = blockIdx.x * 256 + threadIdx.x;
    if (t >= PRE_N) return;
    unsigned long long key = g_keys_sorted[t];
    int a = (int)(key & 0xffffffffu);
    ((float4*)g_topbox)[t] = ((const float4*)g_bbox)[a];
    g_topprob[t] = __uint_as_float(~(unsigned)(key >> 32));
}

// ---------------- NMS suppression bitmask ----------------
__global__ void nms_mask_kernel() {
    const int rb = blockIdx.y, cb = blockIdx.x;
    if (cb < rb) return;
    __shared__ float4 cboxes[64];
    int cstart = cb * 64;
    int csize  = min(64, PRE_N - cstart);
    int t = threadIdx.x;
    if (t < csize) cboxes[t] = ((const float4*)g_topbox)[cstart + t];
    __syncthreads();

    int i = rb * 64 + t;
    if (i >= PRE_N) return;
    float4 b = ((const float4*)g_topbox)[i];
    float areai = (b.z - b.x + 1.f) * (b.w - b.y + 1.f);

    unsigned long long m = 0ull;
    int js = (rb == cb) ? t + 1 : 0;
    for (int j = js; j < csize; j++) {
        float4 c = cboxes[j];
        float iw = fminf(b.z, c.z) - fmaxf(b.x, c.x) + 1.f;
        float ih = fminf(b.w, c.w) - fmaxf(b.y, c.y) + 1.f;
        iw = fmaxf(iw, 0.f);
        ih = fmaxf(ih, 0.f);
        float inter = iw * ih;
        float areaj = (c.z - c.x + 1.f) * (c.w - c.y + 1.f);
        float iou = inter / (areai + areaj - inter);
        if (iou > 0.7f) m |= (1ull << j);
    }
    g_mask[(long long)i * NWORDS + cb] = m;
}

// ---------------- greedy NMS scan (1 block) + write filtered/probs ----------------
__global__ void __launch_bounds__(128) nms_scan_kernel(float* __restrict__ outF,
                                                       float* __restrict__ outP) {
    __shared__ int kept[PRE_N];
    __shared__ unsigned long long mw[64];
    __shared__ unsigned long long remv;
    __shared__ int kc;
    const int tid = threadIdx.x;
    if (tid == 0) kc = 0;
    __syncthreads();

    for (int g = 0; g < NWORDS; g++) {
        if (tid == 0) remv = 0ull;
        __syncthreads();
        unsigned long long part = 0ull;
        for (int t = tid; t < kc; t += 128)
            part |= g_mask[(long long)kept[t] * NWORDS + g];
        if (part) atomicOr(&remv, part);
        if (tid < 64) {
            int i = g*64 + tid;
            mw[tid] = (i < PRE_N) ? g_mask[(long long)i * NWORDS + g] : 0ull;
        }
        __syncthreads();
        if (tid == 0) {
            unsigned long long r = remv;
            int lim = min(64, PRE_N - g*64);
            for (int b = 0; b < lim; b++) {
                if (!((r >> b) & 1ull)) {
                    kept[kc++] = g*64 + b;
                    r |= mw[b];
                }
            }
        }
        __syncthreads();
    }

    for (int rI = tid; rI < POS_N; rI += 128) {
        if (rI < kc) {
            int a = kept[rI];
            outF[rI*4 + 0] = g_topbox[a*4 + 0];
            outF[rI*4 + 1] = g_topbox[a*4 + 1];
            outF[rI*4 + 2] = g_topbox[a*4 + 2];
            outF[rI*4 + 3] = g_topbox[a*4 + 3];
            outP[rI] = g_topprob[a];
        } else {
            outF[rI*4 + 0] = 0.f; outF[rI*4 + 1] = 0.f;
            outF[rI*4 + 2] = 0.f; outF[rI*4 + 3] = 0.f;
            outP[rI] = 0.f;
        }
    }
}

// ---------------- gather proposals[valid_idx], cls[valid_idx] ----------------
__global__ void gather_valid_kernel(const int* __restrict__ vidx, int nv,
                                    float* __restrict__ out) {
    int i = blockIdx.x * 256 + threadIdx.x;
    if (i >= nv) return;
    int a = vidx[i];
    out[i*4 + 0] = g_prop[a*4 + 0];
    out[i*4 + 1] = g_prop[a*4 + 1];
    out[i*4 + 2] = g_prop[a*4 + 2];
    out[i*4 + 3] = g_prop[a*4 + 3];
    int pix = a / 9, k = a % 9;
    out[(long long)nv*4 + i*2 + 0] = g_cls[(k*2 + 0)*NPIX + pix];
    out[(long long)nv*4 + i*2 + 1] = g_cls[(k*2 + 1)*NPIX + pix];
}

// ---------------- host ----------------
extern "C" void kernel_launch(void* const* d_in, const int* in_sizes, int n_in,
                              void* d_out, int out_size) {
    int ix=-1, iwr=-1, ibr=-1, iwc=-1, ibc=-1, iwg=-1, ibg=-1, ian=-1, ivi=-1;
    int nv = (out_size - (POS_N*4 + POS_N)) / 6;
    for (int i = 0; i < n_in; i++) {
        int s = in_sizes[i];
        if      (s == 1024*NPIX)     ix  = i;
        else if (s == 512*1024*9)    iwr = i;
        else if (s == 512)           ibr = i;
        else if (s == 18*512)        iwc = i;
        else if (s == 18)            ibc = i;
        else if (s == 36*512)        iwg = i;
        else if (s == 36)            ibg = i;
        else if (s == NANCH*4)       ian = i;
        else if (s == nv)            ivi = i;
    }
    if (ivi < 0) ivi = 8;

    const float* x      = (const float*)d_in[ix];
    const float* w_rpn  = (const float*)d_in[iwr];
    const float* b_rpn  = (const float*)d_in[ibr];
    const float* w_cls  = (const float*)d_in[iwc];
    const float* b_cls  = (const float*)d_in[ibc];
    const float* w_reg  = (const float*)d_in[iwg];
    const float* b_reg  = (const float*)d_in[ibg];
    const float* anch   = (const float*)d_in[ian];
    const int*   vidx   = (const int*)d_in[ivi];
    float* out = (float*)d_out;

    transpose_w_kernel<<<dim3(288, 16), 256>>>(w_rpn);
    conv3x3_kernel<<<dim3(72, 2), 256>>>(x, b_rpn);
    conv1x1_kernel<<<NPIX/256, 256>>>(w_cls, b_cls, w_reg, b_reg);
    decode_kernel<<<NANCH/256, 256>>>(anch);

    void *d_temp, *d_kin, *d_kout;
    cudaGetSymbolAddress(&d_temp, g_cub_temp);
    cudaGetSymbolAddress(&d_kin,  g_keys);
    cudaGetSymbolAddress(&d_kout, g_keys_sorted);
    size_t temp_bytes = sizeof(g_cub_temp);
    cub::DeviceRadixSort::SortKeys(d_temp, temp_bytes,
                                   (const unsigned long long*)d_kin,
                                   (unsigned long long*)d_kout,
                                   NANCH, 0, 64, (cudaStream_t)0);

    gather_top_kernel<<<(PRE_N + 255)/256, 256>>>();
    nms_mask_kernel<<<dim3(NWORDS, NWORDS), 64>>>();
    nms_scan_kernel<<<1, 128>>>(out + (long long)nv*6,
                                out + (long long)nv*6 + POS_N*4);
    gather_valid_kernel<<<(nv + 255)/256, 256>>>(vidx, nv, out);
}